// round 1
// baseline (speedup 1.0000x reference)
#include <cuda_runtime.h>

#define HW   16384
#define CDIM 192
#define C3   576
#define BATCH 8
#define HEADS 8
#define CHD  24

// ---------------- scratch (device globals: allocation-free rule) ----------------
__device__ float g_qkv [75497472];   // [8,576,16384] after 1x1 conv
__device__ float g_qkvd[75497472];   // [8,576,16384] after depthwise 3x3
__device__ float g_var [BATCH*CDIM];
__device__ float g_norm[BATCH*384];  // sumsq for q (0..191) and k (192..383)
__device__ float g_S   [BATCH*HEADS*CHD*CHD];
__device__ float g_M   [BATCH*CDIM*CDIM];

// ---------------- zero the split-K accumulator ----------------
__global__ void k_zeroS() {
    int i = blockIdx.x * blockDim.x + threadIdx.x;
    if (i < BATCH*HEADS*CHD*CHD) g_S[i] = 0.f;
}

// ---------------- depthwise 3x3 on x + unbiased variance per (b,c) ----------------
__global__ __launch_bounds__(256) void k_dw_var(const float* __restrict__ x,
                                                const float* __restrict__ wdw)
{
    __shared__ float s[66*130];
    __shared__ float red[64];
    const int bc = blockIdx.x;                 // b*192 + c
    const float* plane = x + (size_t)bc * HW;
    const int c = bc % CDIM;
    const int tid = threadIdx.x;
    float w9[9];
    #pragma unroll
    for (int i = 0; i < 9; i++) w9[i] = wdw[c*9 + i];
    float sum = 0.f, sq = 0.f;
    for (int half = 0; half < 2; half++) {
        if (half) __syncthreads();
        const int y0 = half * 64;
        for (int i = tid; i < 66*130; i += 256) {
            int r = i / 130, cc = i % 130;
            int y = y0 + r - 1, xx = cc - 1;
            s[i] = (y >= 0 && y < 128 && (unsigned)xx < 128u) ? plane[y*128 + xx] : 0.f;
        }
        __syncthreads();
        for (int p = tid; p < 8192; p += 256) {
            int yl = p >> 7, xx = p & 127;
            const float* bp = &s[yl*130 + xx];
            float v = bp[0]*w9[0]   + bp[1]*w9[1]   + bp[2]*w9[2]
                    + bp[130]*w9[3] + bp[131]*w9[4] + bp[132]*w9[5]
                    + bp[260]*w9[6] + bp[261]*w9[7] + bp[262]*w9[8];
            sum += v; sq += v*v;
        }
    }
    #pragma unroll
    for (int o = 16; o > 0; o >>= 1) {
        sum += __shfl_down_sync(0xffffffffu, sum, o);
        sq  += __shfl_down_sync(0xffffffffu, sq,  o);
    }
    if ((tid & 31) == 0) { red[tid>>5] = sum; red[32 + (tid>>5)] = sq; }
    __syncthreads();
    if (tid == 0) {
        float S = 0.f, Q = 0.f;
        #pragma unroll
        for (int i = 0; i < 8; i++) { S += red[i]; Q += red[32+i]; }
        g_var[bc] = (Q - S*S*(1.f/16384.f)) * (1.f/16383.f);  // ddof=1
    }
}

// ---------------- depthwise 3x3 on qkv + l2 sumsq for q,k channels ----------------
__global__ __launch_bounds__(256) void k_dw_qkv(const float* __restrict__ wdw)
{
    __shared__ float s[66*130];
    __shared__ float red[32];
    const int bc = blockIdx.x;                  // b*576 + ch
    const float* plane = g_qkv  + (size_t)bc * HW;
    float*       outp  = g_qkvd + (size_t)bc * HW;
    const int ch = bc % C3;
    const int b  = bc / C3;
    const int tid = threadIdx.x;
    float w9[9];
    #pragma unroll
    for (int i = 0; i < 9; i++) w9[i] = wdw[ch*9 + i];
    float sq = 0.f;
    for (int half = 0; half < 2; half++) {
        if (half) __syncthreads();
        const int y0 = half * 64;
        for (int i = tid; i < 66*130; i += 256) {
            int r = i / 130, cc = i % 130;
            int y = y0 + r - 1, xx = cc - 1;
            s[i] = (y >= 0 && y < 128 && (unsigned)xx < 128u) ? plane[y*128 + xx] : 0.f;
        }
        __syncthreads();
        for (int p = tid; p < 8192; p += 256) {
            int yl = p >> 7, xx = p & 127;
            const float* bp = &s[yl*130 + xx];
            float v = bp[0]*w9[0]   + bp[1]*w9[1]   + bp[2]*w9[2]
                    + bp[130]*w9[3] + bp[131]*w9[4] + bp[132]*w9[5]
                    + bp[260]*w9[6] + bp[261]*w9[7] + bp[262]*w9[8];
            outp[(y0 + yl)*128 + xx] = v;
            sq += v*v;
        }
    }
    #pragma unroll
    for (int o = 16; o > 0; o >>= 1) sq += __shfl_down_sync(0xffffffffu, sq, o);
    if ((tid & 31) == 0) red[tid>>5] = sq;
    __syncthreads();
    if (tid == 0 && ch < 384) {
        float Q = 0.f;
        #pragma unroll
        for (int i = 0; i < 8; i++) Q += red[i];
        g_norm[b*384 + ch] = Q;
    }
}

// ---------------- S = q @ k^T per (b,h), split-K with atomics ----------------
__global__ __launch_bounds__(144) void k_qk()
{
    __shared__ float qs[24][64];
    __shared__ float ks[24][64];
    const int bh = blockIdx.x;
    const int b = bh >> 3, h = bh & 7;
    const float* qb = g_qkvd + ((size_t)b*C3 + h*CHD) * HW;
    const float* kb = g_qkvd + ((size_t)b*C3 + 192 + h*CHD) * HW;
    const int n0 = blockIdx.y * 1024;
    const int tid = threadIdx.x;
    const int sub = tid & 3;
    const int cd  = tid >> 2;          // 0..35
    const int c0 = (cd / 6) * 4, d0 = (cd % 6) * 4;
    float acc[4][4] = {};
    for (int chk = 0; chk < 16; chk++) {
        if (chk) __syncthreads();
        const int nn = n0 + chk * 64;
        for (int i = tid; i < 24*64; i += 144) {
            int r = i >> 6, j = i & 63;
            qs[r][j] = qb[(size_t)r*HW + nn + j];
            ks[r][j] = kb[(size_t)r*HW + nn + j];
        }
        __syncthreads();
        const int j0 = sub * 16;
        #pragma unroll 4
        for (int j = j0; j < j0 + 16; j++) {
            float q0 = qs[c0+0][j], q1 = qs[c0+1][j], q2 = qs[c0+2][j], q3 = qs[c0+3][j];
            float k0 = ks[d0+0][j], k1 = ks[d0+1][j], k2 = ks[d0+2][j], k3 = ks[d0+3][j];
            acc[0][0] += q0*k0; acc[0][1] += q0*k1; acc[0][2] += q0*k2; acc[0][3] += q0*k3;
            acc[1][0] += q1*k0; acc[1][1] += q1*k1; acc[1][2] += q1*k2; acc[1][3] += q1*k3;
            acc[2][0] += q2*k0; acc[2][1] += q2*k1; acc[2][2] += q2*k2; acc[2][3] += q2*k3;
            acc[3][0] += q3*k0; acc[3][1] += q3*k1; acc[3][2] += q3*k2; acc[3][3] += q3*k3;
        }
    }
    #pragma unroll
    for (int i = 0; i < 4; i++)
        #pragma unroll
        for (int l = 0; l < 4; l++)
            atomicAdd(&g_S[(size_t)bh*576 + (c0+i)*24 + (d0+l)], acc[i][l]);
}

// ---------------- softmax (with norms, temp, diag var bias) + M = Wproj @ blockdiag(attn) ----------------
__global__ __launch_bounds__(192) void k_soft(const float* __restrict__ temp,
                                              const float* __restrict__ resc,
                                              const float* __restrict__ wproj)
{
    __shared__ float a[24][24];
    const int h = blockIdx.x, b = blockIdx.y;
    const int tid = threadIdx.x;
    const float* Sp = g_S + (size_t)(b*8 + h) * 576;
    const float t = temp[h];
    for (int idx = tid; idx < 576; idx += 192) {
        int c = idx / 24, d = idx % 24;
        float nq = sqrtf(g_norm[b*384 + h*24 + c]);
        float nk = sqrtf(g_norm[b*384 + 192 + h*24 + d]);
        float denom = fmaxf(nq, 1e-12f) * fmaxf(nk, 1e-12f);
        float l = Sp[idx] / denom * t;
        if (c == d) l += resc[h] * g_var[b*192 + h*24 + c];
        a[c][d] = l;
    }
    __syncthreads();
    if (tid < 24) {
        const int c = tid;
        float m = -1e30f;
        #pragma unroll
        for (int d = 0; d < 24; d++) m = fmaxf(m, a[c][d]);
        float e[24]; float ssum = 0.f;
        #pragma unroll
        for (int d = 0; d < 24; d++) { e[d] = expf(a[c][d] - m); ssum += e[d]; }
        float inv = 1.f / ssum;
        #pragma unroll
        for (int d = 0; d < 24; d++) a[c][d] = e[d] * inv;
    }
    __syncthreads();
    const int co = tid;   // 0..191
    float wr[24];
    #pragma unroll
    for (int c = 0; c < 24; c++) wr[c] = wproj[(size_t)co*CDIM + h*24 + c];
    float* Mp = g_M + (size_t)b*CDIM*CDIM + (size_t)co*CDIM + h*24;
    #pragma unroll 4
    for (int d = 0; d < 24; d++) {
        float accv = 0.f;
        #pragma unroll
        for (int c = 0; c < 24; c++) accv += wr[c] * a[c][d];
        Mp[d] = accv;
    }
}

// ---------------- batched SGEMM C[M,N] = A[M,K] @ B[K,N], fp32 with FFMA2 (f32x2) ----------------
// BM=64, BN=128, BK=16, 128 threads, 8x8 per-thread tile packed into f32x2 accumulators.
__global__ __launch_bounds__(128) void sgemm64x128(
    const float* __restrict__ A, const float* __restrict__ Bm, float* __restrict__ C,
    int M, int N, int K, long long sA, long long sB, long long sC)
{
    const float* Ab = A  + (long long)blockIdx.z * sA;
    const float* Bb = Bm + (long long)blockIdx.z * sB;
    float*       Cb = C  + (long long)blockIdx.z * sC;
    const int bm = blockIdx.y * 64;
    const int bn = blockIdx.x * 128;
    __shared__ float As[16][68];    // [k][m], padded to kill STS conflicts
    __shared__ float Bs[16][128];   // [k][n]
    const int tid = threadIdx.x;
    const int tx = tid & 15;        // 16 col groups
    const int ty = tid >> 4;        // 8 row groups
    unsigned long long acc[8][4] = {};   // 8 rows x 4 col-pairs (f32x2)
    const int arow = tid >> 1;
    const int acol = (tid & 1) ? 8 : 0;

    for (int k0 = 0; k0 < K; k0 += 16) {
        // load A tile 64x16 (transposed into As[k][m])
        {
            const float* ap = &Ab[(size_t)(bm + arow)*K + k0 + acol];
            float4 a0 = *(const float4*)ap;
            float4 a1 = *(const float4*)(ap + 4);
            As[acol+0][arow] = a0.x; As[acol+1][arow] = a0.y;
            As[acol+2][arow] = a0.z; As[acol+3][arow] = a0.w;
            As[acol+4][arow] = a1.x; As[acol+5][arow] = a1.y;
            As[acol+6][arow] = a1.z; As[acol+7][arow] = a1.w;
        }
        // load B tile 16x128
        #pragma unroll
        for (int i = 0; i < 4; i++) {
            int idx = tid + i*128;
            int kr = idx >> 5;
            int nc = (idx & 31) << 2;
            *(float4*)&Bs[kr][nc] = *(const float4*)&Bb[(size_t)(k0 + kr)*N + bn + nc];
        }
        __syncthreads();
        #pragma unroll
        for (int kk = 0; kk < 16; kk++) {
            float4 a0 = *(const float4*)&As[kk][ty*8];
            float4 a1 = *(const float4*)&As[kk][ty*8 + 4];
            ulonglong2 b0 = *(const ulonglong2*)&Bs[kk][tx*8];
            ulonglong2 b1 = *(const ulonglong2*)&Bs[kk][tx*8 + 4];
            unsigned long long bv0 = b0.x, bv1 = b0.y, bv2 = b1.x, bv3 = b1.y;
            float av[8] = {a0.x,a0.y,a0.z,a0.w,a1.x,a1.y,a1.z,a1.w};
            #pragma unroll
            for (int i = 0; i < 8; i++) {
                unsigned int u = __float_as_uint(av[i]);
                unsigned long long ad;
                asm("mov.b64 %0, {%1, %1};" : "=l"(ad) : "r"(u));
                asm("fma.rn.f32x2 %0, %1, %2, %0;" : "+l"(acc[i][0]) : "l"(ad), "l"(bv0));
                asm("fma.rn.f32x2 %0, %1, %2, %0;" : "+l"(acc[i][1]) : "l"(ad), "l"(bv1));
                asm("fma.rn.f32x2 %0, %1, %2, %0;" : "+l"(acc[i][2]) : "l"(ad), "l"(bv2));
                asm("fma.rn.f32x2 %0, %1, %2, %0;" : "+l"(acc[i][3]) : "l"(ad), "l"(bv3));
            }
        }
        __syncthreads();
    }
    #pragma unroll
    for (int i = 0; i < 8; i++) {
        float* cp = &Cb[(size_t)(bm + ty*8 + i)*N + bn + tx*8];
        ulonglong2 s0, s1;
        s0.x = acc[i][0]; s0.y = acc[i][1];
        s1.x = acc[i][2]; s1.y = acc[i][3];
        *(ulonglong2*)cp       = s0;
        *(ulonglong2*)(cp + 4) = s1;
    }
}

// ---------------- launch ----------------
extern "C" void kernel_launch(void* const* d_in, const int* in_sizes, int n_in,
                              void* d_out, int out_size)
{
    const float* x       = (const float*)d_in[0];
    const float* w_dw    = (const float*)d_in[1];
    const float* w_qkv   = (const float*)d_in[2];
    const float* w_qkvdw = (const float*)d_in[3];
    const float* w_proj  = (const float*)d_in[4];
    const float* temp    = (const float*)d_in[5];
    const float* resc    = (const float*)d_in[6];
    float* out = (float*)d_out;

    float *qkvp, *qkvdp, *Mp;
    cudaGetSymbolAddress((void**)&qkvp,  g_qkv);
    cudaGetSymbolAddress((void**)&qkvdp, g_qkvd);
    cudaGetSymbolAddress((void**)&Mp,    g_M);

    k_zeroS<<<36, 1024>>>();
    k_dw_var<<<BATCH*CDIM, 256>>>(x, w_dw);
    // qkv 1x1 conv: per batch [576,16384] = W[576,192] @ x[b][192,16384]
    sgemm64x128<<<dim3(128, 9, BATCH), 128>>>(w_qkv, x, qkvp,
        C3, HW, CDIM, 0LL, (long long)CDIM*HW, (long long)C3*HW);
    k_dw_qkv<<<BATCH*C3, 256>>>(w_qkvdw);
    k_qk<<<dim3(64, 16), 144>>>();
    k_soft<<<dim3(HEADS, BATCH), 192>>>(temp, resc, w_proj);
    // final: out[b] = M[b](192x192) @ V[b](192x16384), V = qkvd channels 384..575
    sgemm64x128<<<dim3(128, 3, BATCH), 128>>>(Mp, qkvdp + (size_t)384*HW, out,
        CDIM, HW, CDIM, (long long)CDIM*CDIM, (long long)C3*HW, (long long)CDIM*HW);
}

// round 3
// speedup vs baseline: 1.6950x; 1.6950x over previous
#include <cuda_runtime.h>
#include <cstdint>

#define HW   16384
#define CDIM 192
#define C3   576
#define BATCH 8
#define HEADS 8
#define CHD  24

// ---------------- scratch (device globals: allocation-free rule) ----------------
__device__ float g_qkv [75497472];   // [8,576,16384] after 1x1 conv
__device__ float g_qkvd[75497472];   // [8,576,16384] after depthwise 3x3
__device__ float g_var [BATCH*CDIM];
__device__ float g_norm[BATCH*384];  // sumsq for q (0..191) and k (192..383)
__device__ float g_S   [BATCH*HEADS*CHD*CHD];
__device__ float g_M   [BATCH*CDIM*CDIM];

__device__ __forceinline__ uint32_t smem_u32(const void* p) {
    uint32_t a;
    asm("{ .reg .u64 t; cvta.to.shared.u64 t, %1; cvt.u32.u64 %0, t; }" : "=r"(a) : "l"(p));
    return a;
}
__device__ __forceinline__ uint32_t f2tf32(float f) {
    uint32_t o;
    asm("cvt.rna.tf32.f32 %0, %1;" : "=r"(o) : "f"(f));
    return o;
}
__device__ __forceinline__ void mma_tf32(float* c, const uint32_t* a, const uint32_t* b) {
    asm volatile(
        "mma.sync.aligned.m16n8k8.row.col.f32.tf32.tf32.f32 "
        "{%0,%1,%2,%3}, {%4,%5,%6,%7}, {%8,%9}, {%0,%1,%2,%3};"
        : "+f"(c[0]), "+f"(c[1]), "+f"(c[2]), "+f"(c[3])
        : "r"(a[0]), "r"(a[1]), "r"(a[2]), "r"(a[3]), "r"(b[0]), "r"(b[1]));
}
__device__ __forceinline__ void cp_async16(uint32_t dst, const void* src) {
    asm volatile("cp.async.cg.shared.global [%0], [%1], 16;" :: "r"(dst), "l"(src) : "memory");
}

// ================= tf32 mma.sync batched GEMM: C[M,N] = A[M,K] @ B[K,N] =================
// BM=64, BN=256, BK=16. 256 threads = 8 warps, each warp owns a 64x32 N-slice.
// SMEM strides: As 72 (72%32==8), Bs 264 (264%32==8) -> all frag LDS/STS conflict-free.
__global__ void __launch_bounds__(256, 2) gemm_mma(
    const float* __restrict__ A, const float* __restrict__ B, float* __restrict__ C,
    int M, int N, int K, long long sA, long long sB, long long sC)
{
    __shared__ float As[2][16][72];
    __shared__ float Bs[2][16][264];
    const int tid  = threadIdx.x;
    const int lane = tid & 31;
    const int wid  = tid >> 5;            // n-warp 0..7
    const int g    = lane >> 2;           // groupID
    const int t    = lane & 3;            // thread-in-group
    const float* Ab = A + (long long)blockIdx.z * sA;
    const float* Bb = B + (long long)blockIdx.z * sB;
    float*       Cb = C + (long long)blockIdx.z * sC;
    const int bm = blockIdx.y * 64;
    const int bn = blockIdx.x * 256;

    const int am    = tid & 63;           // A tile row owned by this thread
    const int ak    = (tid >> 6) << 2;    // A k-quad base (0,4,8,12)
    const int bnoff = (tid & 63) << 2;    // B col offset (float4 chunk)
    const int bk    = tid >> 6;           // B k-row base (+4 per pass)

    float acc[4][4][4];
    #pragma unroll
    for (int i = 0; i < 4; i++)
        #pragma unroll
        for (int j = 0; j < 4; j++)
            #pragma unroll
            for (int l = 0; l < 4; l++) acc[i][j][l] = 0.f;

    // ---- preload stage 0 ----
    float4 areg = *(const float4*)&Ab[(size_t)(bm + am) * K + ak];
    #pragma unroll
    for (int p = 0; p < 4; p++)
        cp_async16(smem_u32(&Bs[0][bk + p * 4][bnoff]),
                   &Bb[(size_t)(bk + p * 4) * N + bn + bnoff]);
    asm volatile("cp.async.commit_group;" ::: "memory");
    As[0][ak + 0][am] = __uint_as_float(f2tf32(areg.x));
    As[0][ak + 1][am] = __uint_as_float(f2tf32(areg.y));
    As[0][ak + 2][am] = __uint_as_float(f2tf32(areg.z));
    As[0][ak + 3][am] = __uint_as_float(f2tf32(areg.w));
    asm volatile("cp.async.wait_group 0;" ::: "memory");
    __syncthreads();

    const int nk = K >> 4;     // 12
    for (int i = 0; i < nk; i++) {
        const int s = i & 1;
        float4 anext;
        if (i + 1 < nk) {
            const int k0 = (i + 1) << 4;
            anext = *(const float4*)&Ab[(size_t)(bm + am) * K + k0 + ak];
            #pragma unroll
            for (int p = 0; p < 4; p++)
                cp_async16(smem_u32(&Bs[s ^ 1][bk + p * 4][bnoff]),
                           &Bb[(size_t)(k0 + bk + p * 4) * N + bn + bnoff]);
            asm volatile("cp.async.commit_group;" ::: "memory");
        }
        // ---- compute on stage s ----
        #pragma unroll
        for (int kk = 0; kk < 2; kk++) {
            uint32_t af[4][4];
            #pragma unroll
            for (int ma = 0; ma < 4; ma++) {
                af[ma][0] = __float_as_uint(As[s][kk * 8 + t    ][ma * 16 + g    ]);
                af[ma][1] = __float_as_uint(As[s][kk * 8 + t    ][ma * 16 + g + 8]);
                af[ma][2] = __float_as_uint(As[s][kk * 8 + t + 4][ma * 16 + g    ]);
                af[ma][3] = __float_as_uint(As[s][kk * 8 + t + 4][ma * 16 + g + 8]);
            }
            uint32_t bf[4][2];
            #pragma unroll
            for (int na = 0; na < 4; na++) {
                bf[na][0] = f2tf32(Bs[s][kk * 8 + t    ][wid * 32 + na * 8 + g]);
                bf[na][1] = f2tf32(Bs[s][kk * 8 + t + 4][wid * 32 + na * 8 + g]);
            }
            #pragma unroll
            for (int ma = 0; ma < 4; ma++)
                #pragma unroll
                for (int na = 0; na < 4; na++)
                    mma_tf32(acc[ma][na], af[ma], bf[na]);
        }
        if (i + 1 < nk) {
            As[s ^ 1][ak + 0][am] = __uint_as_float(f2tf32(anext.x));
            As[s ^ 1][ak + 1][am] = __uint_as_float(f2tf32(anext.y));
            As[s ^ 1][ak + 2][am] = __uint_as_float(f2tf32(anext.z));
            As[s ^ 1][ak + 3][am] = __uint_as_float(f2tf32(anext.w));
            asm volatile("cp.async.wait_group 0;" ::: "memory");
        }
        __syncthreads();
    }
    // ---- epilogue: direct float2 stores (32B sectors fully used) ----
    #pragma unroll
    for (int ma = 0; ma < 4; ma++) {
        #pragma unroll
        for (int na = 0; na < 4; na++) {
            const int row = bm + ma * 16 + g;
            const int col = bn + wid * 32 + na * 8 + (t << 1);
            float2 v0 = make_float2(acc[ma][na][0], acc[ma][na][1]);
            float2 v1 = make_float2(acc[ma][na][2], acc[ma][na][3]);
            *(float2*)&Cb[(size_t)row * N + col]       = v0;
            *(float2*)&Cb[(size_t)(row + 8) * N + col] = v1;
        }
    }
}

// ---------------- zero the split-K accumulator ----------------
__global__ void k_zeroS() {
    int i = blockIdx.x * blockDim.x + threadIdx.x;
    if (i < BATCH*HEADS*CHD*CHD) g_S[i] = 0.f;
}

// ---------------- depthwise 3x3 on x + unbiased variance per (b,c) ----------------
__global__ __launch_bounds__(256) void k_dw_var(const float* __restrict__ x,
                                                const float* __restrict__ wdw)
{
    __shared__ float s[66*130];
    __shared__ float red[64];
    const int bc = blockIdx.x;
    const float* plane = x + (size_t)bc * HW;
    const int c = bc % CDIM;
    const int tid = threadIdx.x;
    float w9[9];
    #pragma unroll
    for (int i = 0; i < 9; i++) w9[i] = wdw[c*9 + i];
    float sum = 0.f, sq = 0.f;
    for (int half = 0; half < 2; half++) {
        if (half) __syncthreads();
        const int y0 = half * 64;
        for (int i = tid; i < 66*130; i += 256) {
            int r = i / 130, cc = i % 130;
            int y = y0 + r - 1, xx = cc - 1;
            s[i] = (y >= 0 && y < 128 && (unsigned)xx < 128u) ? plane[y*128 + xx] : 0.f;
        }
        __syncthreads();
        for (int p = tid; p < 8192; p += 256) {
            int yl = p >> 7, xx = p & 127;
            const float* bp = &s[yl*130 + xx];
            float v = bp[0]*w9[0]   + bp[1]*w9[1]   + bp[2]*w9[2]
                    + bp[130]*w9[3] + bp[131]*w9[4] + bp[132]*w9[5]
                    + bp[260]*w9[6] + bp[261]*w9[7] + bp[262]*w9[8];
            sum += v; sq += v*v;
        }
    }
    #pragma unroll
    for (int o = 16; o > 0; o >>= 1) {
        sum += __shfl_down_sync(0xffffffffu, sum, o);
        sq  += __shfl_down_sync(0xffffffffu, sq,  o);
    }
    if ((tid & 31) == 0) { red[tid>>5] = sum; red[32 + (tid>>5)] = sq; }
    __syncthreads();
    if (tid == 0) {
        float S = 0.f, Q = 0.f;
        #pragma unroll
        for (int i = 0; i < 8; i++) { S += red[i]; Q += red[32+i]; }
        g_var[bc] = (Q - S*S*(1.f/16384.f)) * (1.f/16383.f);
    }
}

// ---------------- depthwise 3x3 on qkv + l2 sumsq for q,k channels ----------------
__global__ __launch_bounds__(256) void k_dw_qkv(const float* __restrict__ wdw)
{
    __shared__ float s[66*130];
    __shared__ float red[32];
    const int bc = blockIdx.x;
    const float* plane = g_qkv  + (size_t)bc * HW;
    float*       outp  = g_qkvd + (size_t)bc * HW;
    const int ch = bc % C3;
    const int b  = bc / C3;
    const int tid = threadIdx.x;
    float w9[9];
    #pragma unroll
    for (int i = 0; i < 9; i++) w9[i] = wdw[ch*9 + i];
    float sq = 0.f;
    for (int half = 0; half < 2; half++) {
        if (half) __syncthreads();
        const int y0 = half * 64;
        for (int i = tid; i < 66*130; i += 256) {
            int r = i / 130, cc = i % 130;
            int y = y0 + r - 1, xx = cc - 1;
            s[i] = (y >= 0 && y < 128 && (unsigned)xx < 128u) ? plane[y*128 + xx] : 0.f;
        }
        __syncthreads();
        for (int p = tid; p < 8192; p += 256) {
            int yl = p >> 7, xx = p & 127;
            const float* bp = &s[yl*130 + xx];
            float v = bp[0]*w9[0]   + bp[1]*w9[1]   + bp[2]*w9[2]
                    + bp[130]*w9[3] + bp[131]*w9[4] + bp[132]*w9[5]
                    + bp[260]*w9[6] + bp[261]*w9[7] + bp[262]*w9[8];
            outp[(y0 + yl)*128 + xx] = v;
            sq += v*v;
        }
    }
    #pragma unroll
    for (int o = 16; o > 0; o >>= 1) sq += __shfl_down_sync(0xffffffffu, sq, o);
    if ((tid & 31) == 0) red[tid>>5] = sq;
    __syncthreads();
    if (tid == 0 && ch < 384) {
        float Q = 0.f;
        #pragma unroll
        for (int i = 0; i < 8; i++) Q += red[i];
        g_norm[b*384 + ch] = Q;
    }
}

// ---------------- S = q @ k^T per (b,h), split-K with atomics ----------------
__global__ __launch_bounds__(144) void k_qk()
{
    __shared__ float qs[24][64];
    __shared__ float ks[24][64];
    const int bh = blockIdx.x;
    const int b = bh >> 3, h = bh & 7;
    const float* qb = g_qkvd + ((size_t)b*C3 + h*CHD) * HW;
    const float* kb = g_qkvd + ((size_t)b*C3 + 192 + h*CHD) * HW;
    const int n0 = blockIdx.y * 1024;
    const int tid = threadIdx.x;
    const int sub = tid & 3;
    const int cd  = tid >> 2;
    const int c0 = (cd / 6) * 4, d0 = (cd % 6) * 4;
    float acc[4][4] = {};
    for (int chk = 0; chk < 16; chk++) {
        if (chk) __syncthreads();
        const int nn = n0 + chk * 64;
        for (int i = tid; i < 24*64; i += 144) {
            int r = i >> 6, j = i & 63;
            qs[r][j] = qb[(size_t)r*HW + nn + j];
            ks[r][j] = kb[(size_t)r*HW + nn + j];
        }
        __syncthreads();
        const int j0 = sub * 16;
        #pragma unroll 4
        for (int j = j0; j < j0 + 16; j++) {
            float q0 = qs[c0+0][j], q1 = qs[c0+1][j], q2 = qs[c0+2][j], q3 = qs[c0+3][j];
            float k0 = ks[d0+0][j], k1 = ks[d0+1][j], k2 = ks[d0+2][j], k3 = ks[d0+3][j];
            acc[0][0] += q0*k0; acc[0][1] += q0*k1; acc[0][2] += q0*k2; acc[0][3] += q0*k3;
            acc[1][0] += q1*k0; acc[1][1] += q1*k1; acc[1][2] += q1*k2; acc[1][3] += q1*k3;
            acc[2][0] += q2*k0; acc[2][1] += q2*k1; acc[2][2] += q2*k2; acc[2][3] += q2*k3;
            acc[3][0] += q3*k0; acc[3][1] += q3*k1; acc[3][2] += q3*k2; acc[3][3] += q3*k3;
        }
    }
    #pragma unroll
    for (int i = 0; i < 4; i++)
        #pragma unroll
        for (int l = 0; l < 4; l++)
            atomicAdd(&g_S[(size_t)bh*576 + (c0+i)*24 + (d0+l)], acc[i][l]);
}

// ---------------- softmax + M = Wproj @ blockdiag(attn) ----------------
__global__ __launch_bounds__(192) void k_soft(const float* __restrict__ temp,
                                              const float* __restrict__ resc,
                                              const float* __restrict__ wproj)
{
    __shared__ float a[24][24];
    const int h = blockIdx.x, b = blockIdx.y;
    const int tid = threadIdx.x;
    const float* Sp = g_S + (size_t)(b*8 + h) * 576;
    const float t = temp[h];
    for (int idx = tid; idx < 576; idx += 192) {
        int c = idx / 24, d = idx % 24;
        float nq = sqrtf(g_norm[b*384 + h*24 + c]);
        float nk = sqrtf(g_norm[b*384 + 192 + h*24 + d]);
        float denom = fmaxf(nq, 1e-12f) * fmaxf(nk, 1e-12f);
        float l = Sp[idx] / denom * t;
        if (c == d) l += resc[h] * g_var[b*192 + h*24 + c];
        a[c][d] = l;
    }
    __syncthreads();
    if (tid < 24) {
        const int c = tid;
        float m = -1e30f;
        #pragma unroll
        for (int d = 0; d < 24; d++) m = fmaxf(m, a[c][d]);
        float e[24]; float ssum = 0.f;
        #pragma unroll
        for (int d = 0; d < 24; d++) { e[d] = expf(a[c][d] - m); ssum += e[d]; }
        float inv = 1.f / ssum;
        #pragma unroll
        for (int d = 0; d < 24; d++) a[c][d] = e[d] * inv;
    }
    __syncthreads();
    const int co = tid;
    float wr[24];
    #pragma unroll
    for (int c = 0; c < 24; c++) wr[c] = wproj[(size_t)co*CDIM + h*24 + c];
    float* Mp = g_M + (size_t)b*CDIM*CDIM + (size_t)co*CDIM + h*24;
    #pragma unroll 4
    for (int d = 0; d < 24; d++) {
        float accv = 0.f;
        #pragma unroll
        for (int c = 0; c < 24; c++) accv += wr[c] * a[c][d];
        Mp[d] = accv;
    }
}

// ---------------- launch ----------------
extern "C" void kernel_launch(void* const* d_in, const int* in_sizes, int n_in,
                              void* d_out, int out_size)
{
    const float* x       = (const float*)d_in[0];
    const float* w_dw    = (const float*)d_in[1];
    const float* w_qkv   = (const float*)d_in[2];
    const float* w_qkvdw = (const float*)d_in[3];
    const float* w_proj  = (const float*)d_in[4];
    const float* temp    = (const float*)d_in[5];
    const float* resc    = (const float*)d_in[6];
    float* out = (float*)d_out;

    float *qkvp, *qkvdp, *Mp;
    cudaGetSymbolAddress((void**)&qkvp,  g_qkv);
    cudaGetSymbolAddress((void**)&qkvdp, g_qkvd);
    cudaGetSymbolAddress((void**)&Mp,    g_M);

    // prefer max smem carveout so two 43KB blocks can co-reside
    cudaFuncSetAttribute(gemm_mma, cudaFuncAttributePreferredSharedMemoryCarveout, 90);

    k_zeroS<<<36, 1024>>>();
    k_dw_var<<<BATCH*CDIM, 256>>>(x, w_dw);
    // qkv 1x1 conv: per batch [576,16384] = W[576,192] @ x[b][192,16384]
    gemm_mma<<<dim3(64, 9, BATCH), 256>>>(w_qkv, x, qkvp,
        C3, HW, CDIM, 0LL, (long long)CDIM*HW, (long long)C3*HW);
    k_dw_qkv<<<BATCH*C3, 256>>>(w_qkvdw);
    k_qk<<<dim3(64, 16), 144>>>();
    k_soft<<<dim3(HEADS, BATCH), 192>>>(temp, resc, w_proj);
    // final: out[b] = M[b](192x192) @ V[b](192x16384), V = qkvd channels 384..575
    gemm_mma<<<dim3(64, 3, BATCH), 256>>>(Mp, qkvdp + (size_t)384*HW, out,
        CDIM, HW, CDIM, (long long)CDIM*CDIM, (long long)C3*HW, (long long)CDIM*HW);
}